// round 11
// baseline (speedup 1.0000x reference)
#include <cuda_runtime.h>
#include <cuda_bf16.h>

// Problem constants
#define BB 8
#define LL 8192
#define DD 512
#define SF 4
#define RR 32                 // rows per chunk
#define CH (LL / RR)          // 256 chunks per batch
#define NCHUNK (BB * CH)      // 2048 total chunks
#define OUT_L (LL / SF)       // 2048
#define D4 (DD / 4)           // 128 float4 lanes
#define OUTG (RR / SF)        // 8 output rows per chunk
#define NSUP 16               // supers per batch
#define SUPC (CH / NSUP)      // 16 chunks per super
#define GRIDN 1480            // 148 SMs x 10 blocks, all co-resident

// Scratch (L2-resident)
__device__ float g_part[BB][CH][DD];        // per-chunk aggregates (4 MB)
__device__ float g_sup[BB][NSUP][DD];       // per-super sums (256 KB)
__device__ float g_base[BB][CH][DD];        // per-chunk exclusive bases (4 MB)
__device__ unsigned g_bar;                  // monotonic barrier counter
__device__ unsigned g_tick_a;               // phase-A chunk tickets
__device__ unsigned g_tick_c;               // phase-C chunk tickets
__device__ unsigned g_done;                 // end-of-kernel cleanup counter

__device__ __forceinline__ unsigned ld_acq_u(const unsigned* p) {
    unsigned v;
    asm volatile("ld.acquire.gpu.u32 %0, [%1];" : "=r"(v) : "l"(p) : "memory");
    return v;
}

// Monotonic grid barrier: safe because launch_bounds(128,10) guarantees all
// GRIDN blocks co-resident (1480 = 148*10, smem=0, 40 warps/SM).
__device__ __forceinline__ void gsync(unsigned target) {
    __syncthreads();
    if (threadIdx.x == 0) {
        __threadfence();                       // release prior writes
        atomicAdd(&g_bar, 1u);
        while (ld_acq_u(&g_bar) < target) __nanosleep(32);
    }
    __syncthreads();
    __threadfence();                           // acquire others' writes
}

__global__ __launch_bounds__(128, 10) void k_all(const float* __restrict__ x,
                                                 float* __restrict__ out) {
    const int tid = threadIdx.x;
    const int d4 = tid;
    __shared__ unsigned s_t;

    // ── Phase A: ticket-scheduled per-chunk local scans ──
    for (;;) {
        if (tid == 0) s_t = atomicAdd(&g_tick_a, 1u);
        __syncthreads();
        const unsigned t = s_t;
        __syncthreads();
        if (t >= NCHUNK) break;
        const int b = (int)(t >> 8);
        const int c = (int)(t & (CH - 1));
        const float4* xp = reinterpret_cast<const float4*>(
            x + ((size_t)b * LL + (size_t)c * RR) * DD) + d4;
        float4* op = reinterpret_cast<float4*>(
            out + ((size_t)b * OUT_L + (size_t)c * OUTG) * DD) + d4;

        float4 acc = make_float4(0.f, 0.f, 0.f, 0.f);
#pragma unroll
        for (int g = 0; g < OUTG; ++g) {
            float4 v0 = __ldcs(xp + (size_t)(g * SF + 0) * D4);
            float4 v1 = __ldcs(xp + (size_t)(g * SF + 1) * D4);
            float4 v2 = __ldcs(xp + (size_t)(g * SF + 2) * D4);
            float4 v3 = __ldcs(xp + (size_t)(g * SF + 3) * D4);
            acc.x += (v0.x + v1.x) + (v2.x + v3.x);
            acc.y += (v0.y + v1.y) + (v2.y + v3.y);
            acc.z += (v0.z + v1.z) + (v2.z + v3.z);
            acc.w += (v0.w + v1.w) + (v2.w + v3.w);
            op[(size_t)g * D4] = acc;          // unscaled partial prefix
        }
        reinterpret_cast<float4*>(g_part[b][c])[d4] = acc;
    }

    gsync(GRIDN);

    // ── Phase B1: super sums (128 blocks) ──
    if (blockIdx.x < BB * NSUP) {
        const int b = blockIdx.x >> 4;
        const int s = blockIdx.x & (NSUP - 1);
        float4 sum = make_float4(0.f, 0.f, 0.f, 0.f);
#pragma unroll
        for (int k = 0; k < SUPC; ++k) {
            float4 v = reinterpret_cast<const float4*>(g_part[b][s * SUPC + k])[d4];
            sum.x += v.x; sum.y += v.y; sum.z += v.z; sum.w += v.w;
        }
        reinterpret_cast<float4*>(g_sup[b][s])[d4] = sum;
    }

    gsync(2u * GRIDN);

    // ── Phase B2: per-chunk exclusive bases (128 blocks, one super each) ──
    if (blockIdx.x < BB * NSUP) {
        const int b = blockIdx.x >> 4;
        const int s = blockIdx.x & (NSUP - 1);
        float4 run = make_float4(0.f, 0.f, 0.f, 0.f);
        for (int j = 0; j < s; ++j) {
            float4 v = reinterpret_cast<const float4*>(g_sup[b][j])[d4];
            run.x += v.x; run.y += v.y; run.z += v.z; run.w += v.w;
        }
#pragma unroll
        for (int k = 0; k < SUPC; ++k) {
            const int c = s * SUPC + k;
            reinterpret_cast<float4*>(g_base[b][c])[d4] = run;
            float4 v = reinterpret_cast<const float4*>(g_part[b][c])[d4];
            run.x += v.x; run.y += v.y; run.z += v.z; run.w += v.w;
        }
    }

    gsync(3u * GRIDN);

    // ── Phase C: ticket-scheduled fixup: out = (partial + base) / count ──
    for (;;) {
        if (tid == 0) s_t = atomicAdd(&g_tick_c, 1u);
        __syncthreads();
        const unsigned t = s_t;
        __syncthreads();
        if (t >= NCHUNK) break;
        const int b = (int)(t >> 8);
        const int c = (int)(t & (CH - 1));
        const float4 base = reinterpret_cast<const float4*>(g_base[b][c])[d4];
        float4* op = reinterpret_cast<float4*>(
            out + ((size_t)b * OUT_L + (size_t)c * OUTG) * DD) + d4;
#pragma unroll
        for (int g = 0; g < OUTG; ++g) {
            const float inv = 1.0f / (float)(c * RR + g * SF + SF);
            float4 v = op[(size_t)g * D4];
            v.x = (v.x + base.x) * inv;
            v.y = (v.y + base.y) * inv;
            v.z = (v.z + base.z) * inv;
            v.w = (v.w + base.w) * inv;
            op[(size_t)g * D4] = v;
        }
    }

    // ── Cleanup: last block resets counters for the next graph replay ──
    __syncthreads();
    if (tid == 0) {
        __threadfence();
        unsigned v = atomicAdd(&g_done, 1u);
        if (v == GRIDN - 1) {
            g_bar = 0u; g_tick_a = 0u; g_tick_c = 0u; g_done = 0u;
            __threadfence();
        }
    }
}

extern "C" void kernel_launch(void* const* d_in, const int* in_sizes, int n_in,
                              void* d_out, int out_size) {
    const float* x = (const float*)d_in[0];
    float* out = (float*)d_out;

    k_all<<<GRIDN, 128>>>(x, out);
}

// round 12
// speedup vs baseline: 1.1280x; 1.1280x over previous
#include <cuda_runtime.h>
#include <cuda_bf16.h>

// Problem constants
#define BB 8
#define LL 8192
#define DD 512
#define SF 4
#define RR 32                 // rows per chunk
#define CH (LL / RR)          // 256 chunks per batch
#define NCHUNK (BB * CH)      // 2048 total chunks
#define OUT_L (LL / SF)       // 2048
#define D4 (DD / 4)           // 128 float4 lanes
#define OUTG (RR / SF)        // 8 output rows per chunk
#define NSUP 16               // supers per batch
#define SUPC (CH / NSUP)      // 16 chunks per super
#define GRIDN 1332            // 148 SMs x 9 blocks, all co-resident
#define EXTRA (NCHUNK - GRIDN) // 716 blocks own a second chunk

// Scratch (L2-resident)
__device__ float g_part[BB][CH][DD];        // per-chunk aggregates (4 MB)
__device__ float g_sup[BB][NSUP][DD];       // per-super sums (256 KB)
__device__ float g_base[BB][CH][DD];        // per-chunk exclusive bases (4 MB)
__device__ unsigned g_bar;                  // monotonic barrier counter
__device__ unsigned g_done;                 // end-of-kernel cleanup counter

__device__ __forceinline__ unsigned ld_acq_u(const unsigned* p) {
    unsigned v;
    asm volatile("ld.acquire.gpu.u32 %0, [%1];" : "=r"(v) : "l"(p) : "memory");
    return v;
}

// Monotonic grid barrier: safe because launch_bounds(128,9) guarantees all
// GRIDN = 148*9 blocks are co-resident (smem~0, 36 warps/SM, regs<=56).
__device__ __forceinline__ void gsync(unsigned target) {
    __syncthreads();
    if (threadIdx.x == 0) {
        __threadfence();                       // release prior writes
        atomicAdd(&g_bar, 1u);
        while (ld_acq_u(&g_bar) < target) __nanosleep(256);
    }
    __syncthreads();
    __threadfence();                           // acquire others' writes
}

// Phase A body: local chunk scan; unscaled partials -> out, aggregate -> g_part
__device__ __forceinline__ void do_chunk_a(const float* __restrict__ x,
                                           float* __restrict__ out,
                                           int t, int d4) {
    const int b = t >> 8;
    const int c = t & (CH - 1);
    const float4* xp = reinterpret_cast<const float4*>(
        x + ((size_t)b * LL + (size_t)c * RR) * DD) + d4;
    float4* op = reinterpret_cast<float4*>(
        out + ((size_t)b * OUT_L + (size_t)c * OUTG) * DD) + d4;

    float4 acc = make_float4(0.f, 0.f, 0.f, 0.f);
#pragma unroll
    for (int g = 0; g < OUTG; ++g) {
        float4 v0 = __ldcs(xp + (size_t)(g * SF + 0) * D4);
        float4 v1 = __ldcs(xp + (size_t)(g * SF + 1) * D4);
        float4 v2 = __ldcs(xp + (size_t)(g * SF + 2) * D4);
        float4 v3 = __ldcs(xp + (size_t)(g * SF + 3) * D4);
        acc.x += (v0.x + v1.x) + (v2.x + v3.x);
        acc.y += (v0.y + v1.y) + (v2.y + v3.y);
        acc.z += (v0.z + v1.z) + (v2.z + v3.z);
        acc.w += (v0.w + v1.w) + (v2.w + v3.w);
        op[(size_t)g * D4] = acc;              // unscaled partial prefix
    }
    reinterpret_cast<float4*>(g_part[b][c])[d4] = acc;
}

// Phase C body: out = (partial + base) * 1/count
__device__ __forceinline__ void do_chunk_c(float* __restrict__ out,
                                           int t, int d4) {
    const int b = t >> 8;
    const int c = t & (CH - 1);
    const float4 base = reinterpret_cast<const float4*>(g_base[b][c])[d4];
    float4* op = reinterpret_cast<float4*>(
        out + ((size_t)b * OUT_L + (size_t)c * OUTG) * DD) + d4;
#pragma unroll
    for (int g = 0; g < OUTG; ++g) {
        const float inv = 1.0f / (float)(c * RR + g * SF + SF);
        float4 v = op[(size_t)g * D4];
        v.x = (v.x + base.x) * inv;
        v.y = (v.y + base.y) * inv;
        v.z = (v.z + base.z) * inv;
        v.w = (v.w + base.w) * inv;
        op[(size_t)g * D4] = v;
    }
}

__global__ __launch_bounds__(128, 9) void k_all(const float* __restrict__ x,
                                                float* __restrict__ out) {
    const int tid = threadIdx.x;
    const int d4 = tid;
    const int bid = blockIdx.x;

    // ── Phase A: static chunk assignment (1 or 2 chunks per block) ──
    do_chunk_a(x, out, bid, d4);
    if (bid < EXTRA) do_chunk_a(x, out, GRIDN + bid, d4);

    gsync(GRIDN);

    // ── Phase B1: super sums (blocks 0..127) ──
    if (bid < BB * NSUP) {
        const int b = bid >> 4;
        const int s = bid & (NSUP - 1);
        float4 sum = make_float4(0.f, 0.f, 0.f, 0.f);
#pragma unroll
        for (int k = 0; k < SUPC; ++k) {
            float4 v = reinterpret_cast<const float4*>(g_part[b][s * SUPC + k])[d4];
            sum.x += v.x; sum.y += v.y; sum.z += v.z; sum.w += v.w;
        }
        reinterpret_cast<float4*>(g_sup[b][s])[d4] = sum;
    }

    gsync(2u * GRIDN);

    // ── Phase B2: per-chunk exclusive bases (blocks 0..127, one super each) ──
    if (bid < BB * NSUP) {
        const int b = bid >> 4;
        const int s = bid & (NSUP - 1);
        float4 run = make_float4(0.f, 0.f, 0.f, 0.f);
        for (int j = 0; j < s; ++j) {
            float4 v = reinterpret_cast<const float4*>(g_sup[b][j])[d4];
            run.x += v.x; run.y += v.y; run.z += v.z; run.w += v.w;
        }
#pragma unroll
        for (int k = 0; k < SUPC; ++k) {
            const int c = s * SUPC + k;
            reinterpret_cast<float4*>(g_base[b][c])[d4] = run;
            float4 v = reinterpret_cast<const float4*>(g_part[b][c])[d4];
            run.x += v.x; run.y += v.y; run.z += v.z; run.w += v.w;
        }
    }

    gsync(3u * GRIDN);

    // ── Phase C: static fixup, same assignment as A ──
    do_chunk_c(out, bid, d4);
    if (bid < EXTRA) do_chunk_c(out, GRIDN + bid, d4);

    // ── Cleanup: last block resets counters for the next graph replay ──
    __syncthreads();
    if (tid == 0) {
        __threadfence();
        unsigned v = atomicAdd(&g_done, 1u);
        if (v == GRIDN - 1) {
            g_bar = 0u; g_done = 0u;
            __threadfence();
        }
    }
}

extern "C" void kernel_launch(void* const* d_in, const int* in_sizes, int n_in,
                              void* d_out, int out_size) {
    const float* x = (const float*)d_in[0];
    float* out = (float*)d_out;

    k_all<<<GRIDN, 128>>>(x, out);
}